// round 2
// baseline (speedup 1.0000x reference)
#include <cuda_runtime.h>

#define BB 16
#define NN 4096
#define DD 256
#define EPSF 1e-6f
#define NSPL 16
#define NPER (NN / NSPL)   // 256

// ---------------- scratch (device globals; allocation-free) ----------------
__device__ float g_phi_q[(size_t)BB * NN * DD];   // 64 MB
__device__ float g_phi_k[(size_t)BB * NN * DD];   // 64 MB
__device__ float g_pcs[BB * NSPL * DD];
__device__ float g_pm [BB * NSPL * DD];
__device__ float g_ps [BB * NSPL * DD];
__device__ float g_cs [BB * DD];
__device__ float g_mx [BB * DD];
__device__ float g_sm [BB * DD];
__device__ float g_rs [BB * NN];
__device__ float g_kv [(size_t)BB * DD * DD];     // 4 MB

__device__ __forceinline__ float sigmoidf_(float x) { return 1.f / (1.f + __expf(-x)); }

// ---------------------------------------------------------------------------
// K1: phi = sigmoid(X @ W + b). M = B*N = 65536, N = K = 256.
// 64x64 block tile, 4x4 per thread, BK=16.
// ---------------------------------------------------------------------------
__global__ void __launch_bounds__(256)
k_phi(const float* __restrict__ X, const float* __restrict__ W,
      const float* __restrict__ bias, int which)
{
    __shared__ float As[16][68];   // [k][m], padded
    __shared__ float Bs[16][68];   // [k][e], padded

    float* out = which ? g_phi_k : g_phi_q;

    const int tid = threadIdx.x;
    const int tx = tid & 15, ty = tid >> 4;
    const int m0 = blockIdx.x * 64;
    const int e0 = blockIdx.y * 64;

    const int arow = tid >> 2;
    const int ac4  = (tid & 3) << 2;
    const int brow = tid >> 4;
    const int bc4  = (tid & 15) << 2;

    float acc[4][4];
#pragma unroll
    for (int i = 0; i < 4; i++)
#pragma unroll
        for (int j = 0; j < 4; j++) acc[i][j] = 0.f;

    for (int k0 = 0; k0 < DD; k0 += 16) {
        float4 a = *(const float4*)(X + (size_t)(m0 + arow) * DD + k0 + ac4);
        As[ac4 + 0][arow] = a.x;
        As[ac4 + 1][arow] = a.y;
        As[ac4 + 2][arow] = a.z;
        As[ac4 + 3][arow] = a.w;
        *(float4*)&Bs[brow][bc4] =
            *(const float4*)(W + (size_t)(k0 + brow) * DD + e0 + bc4);
        __syncthreads();

#pragma unroll
        for (int k = 0; k < 16; k++) {
            float4 av = *(const float4*)&As[k][ty << 2];
            float4 bv = *(const float4*)&Bs[k][tx << 2];
            acc[0][0] += av.x * bv.x; acc[0][1] += av.x * bv.y;
            acc[0][2] += av.x * bv.z; acc[0][3] += av.x * bv.w;
            acc[1][0] += av.y * bv.x; acc[1][1] += av.y * bv.y;
            acc[1][2] += av.y * bv.z; acc[1][3] += av.y * bv.w;
            acc[2][0] += av.z * bv.x; acc[2][1] += av.z * bv.y;
            acc[2][2] += av.z * bv.z; acc[2][3] += av.z * bv.w;
            acc[3][0] += av.w * bv.x; acc[3][1] += av.w * bv.y;
            acc[3][2] += av.w * bv.z; acc[3][3] += av.w * bv.w;
        }
        __syncthreads();
    }

#pragma unroll
    for (int i = 0; i < 4; i++) {
        int m = m0 + (ty << 2) + i;
#pragma unroll
        for (int j = 0; j < 4; j++) {
            int e = e0 + (tx << 2) + j;
            out[(size_t)m * DD + e] = sigmoidf_(acc[i][j] + bias[e]);
        }
    }
}

// ---------------------------------------------------------------------------
// K2a: partial column sums of phi_k over n  (per (b, split, e))
// ---------------------------------------------------------------------------
__global__ void __launch_bounds__(256) k_colpart()
{
    const int b = blockIdx.x, spl = blockIdx.y, e = threadIdx.x;
    const float* p = g_phi_k + ((size_t)b * NN + spl * NPER) * DD + e;
    float s = 0.f;
#pragma unroll 8
    for (int n = 0; n < NPER; n++) s += p[(size_t)n * DD];
    g_pcs[(b * NSPL + spl) * DD + e] = s;
}

// K2b: merge partial column sums
__global__ void __launch_bounds__(256) k_csmerge()
{
    const int b = blockIdx.x, e = threadIdx.x;
    float s = 0.f;
#pragma unroll
    for (int spl = 0; spl < NSPL; spl++) s += g_pcs[(b * NSPL + spl) * DD + e];
    g_cs[b * DD + e] = s;
}

// ---------------------------------------------------------------------------
// K3a: partial online softmax stats of x = phi_k * V / (colsum + eps) over n
// ---------------------------------------------------------------------------
__global__ void __launch_bounds__(256) k_statpart(const float* __restrict__ V)
{
    const int b = blockIdx.x, spl = blockIdx.y, e = threadIdx.x;
    const float inv = 1.f / (g_cs[b * DD + e] + EPSF);
    const size_t off = ((size_t)b * NN + spl * NPER) * DD + e;
    const float* pk = g_phi_k + off;
    const float* pv = V + off;

    float mx = -1e30f, s = 0.f;
    for (int n = 0; n < NPER; n++) {
        float x = pk[(size_t)n * DD] * pv[(size_t)n * DD] * inv;
        if (x > mx) {
            s = s * __expf(mx - x) + 1.f;
            mx = x;
        } else {
            s += __expf(x - mx);
        }
    }
    const int idx = (b * NSPL + spl) * DD + e;
    g_pm[idx] = mx;
    g_ps[idx] = s;
}

// K3b: merge partial softmax stats
__global__ void __launch_bounds__(256) k_statmerge()
{
    const int b = blockIdx.x, e = threadIdx.x;
    float M = -1e30f;
#pragma unroll
    for (int spl = 0; spl < NSPL; spl++)
        M = fmaxf(M, g_pm[(b * NSPL + spl) * DD + e]);
    float S = 0.f;
#pragma unroll
    for (int spl = 0; spl < NSPL; spl++) {
        const int idx = (b * NSPL + spl) * DD + e;
        S += g_ps[idx] * __expf(g_pm[idx] - M);
    }
    g_mx[b * DD + e] = M;
    g_sm[b * DD + e] = S;
}

// ---------------------------------------------------------------------------
// K4: row sums of phi_q over d (one warp per row)
// ---------------------------------------------------------------------------
__global__ void __launch_bounds__(256) k_rowsum()
{
    const int row  = blockIdx.x * 8 + (threadIdx.x >> 5);
    const int lane = threadIdx.x & 31;
    const float* p = g_phi_q + (size_t)row * DD;
    float s = 0.f;
#pragma unroll
    for (int i = 0; i < 8; i++) s += p[lane + i * 32];
#pragma unroll
    for (int o = 16; o > 0; o >>= 1) s += __shfl_down_sync(0xffffffffu, s, o);
    if (lane == 0) g_rs[row] = s;
}

// ---------------------------------------------------------------------------
// K5: KV[b,d,e] = sum_n phi_k[b,n,d] * V_b[b,n,e], V_b built on the fly:
//     V_b = exp(phi_k*V/(cs+eps) - m) / s
// 64x64 tile (d x e), BK=32 over n, per-batch.
// ---------------------------------------------------------------------------
__global__ void __launch_bounds__(256) k_kv(const float* __restrict__ V)
{
    __shared__ float As[32][68];   // [n][d]
    __shared__ float Bs[32][68];   // [n][e]  (V_b tile)
    __shared__ float sInv[64], sM[64], sIS[64];

    const int tid = threadIdx.x;
    const int tx = tid & 15, ty = tid >> 4;
    const int d0 = blockIdx.x * 64;
    const int e0 = blockIdx.y * 64;
    const int b  = blockIdx.z;

    if (tid < 64) {
        int e = e0 + tid;
        sInv[tid] = 1.f / (g_cs[b * DD + e] + EPSF);
        sM[tid]   = g_mx[b * DD + e];
        sIS[tid]  = 1.f / g_sm[b * DD + e];
    }
    __syncthreads();

    float acc[4][4];
#pragma unroll
    for (int i = 0; i < 4; i++)
#pragma unroll
        for (int j = 0; j < 4; j++) acc[i][j] = 0.f;

    const size_t base = (size_t)b * NN * DD;

    for (int n0 = 0; n0 < NN; n0 += 32) {
#pragma unroll
        for (int it = 0; it < 2; it++) {
            int idx = tid + it * 256;
            int nl  = idx >> 4;
            int c4  = (idx & 15) << 2;
            size_t off = base + (size_t)(n0 + nl) * DD;

            *(float4*)&As[nl][c4] = *(const float4*)(g_phi_k + off + d0 + c4);

            float4 pk = *(const float4*)(g_phi_k + off + e0 + c4);
            float4 vv = *(const float4*)(V + off + e0 + c4);
            float4 o;
            o.x = __expf(pk.x * vv.x * sInv[c4 + 0] - sM[c4 + 0]) * sIS[c4 + 0];
            o.y = __expf(pk.y * vv.y * sInv[c4 + 1] - sM[c4 + 1]) * sIS[c4 + 1];
            o.z = __expf(pk.z * vv.z * sInv[c4 + 2] - sM[c4 + 2]) * sIS[c4 + 2];
            o.w = __expf(pk.w * vv.w * sInv[c4 + 3] - sM[c4 + 3]) * sIS[c4 + 3];
            *(float4*)&Bs[nl][c4] = o;
        }
        __syncthreads();

#pragma unroll
        for (int k = 0; k < 32; k++) {
            float4 av = *(const float4*)&As[k][ty << 2];
            float4 bv = *(const float4*)&Bs[k][tx << 2];
            acc[0][0] += av.x * bv.x; acc[0][1] += av.x * bv.y;
            acc[0][2] += av.x * bv.z; acc[0][3] += av.x * bv.w;
            acc[1][0] += av.y * bv.x; acc[1][1] += av.y * bv.y;
            acc[1][2] += av.y * bv.z; acc[1][3] += av.y * bv.w;
            acc[2][0] += av.z * bv.x; acc[2][1] += av.z * bv.y;
            acc[2][2] += av.z * bv.z; acc[2][3] += av.z * bv.w;
            acc[3][0] += av.w * bv.x; acc[3][1] += av.w * bv.y;
            acc[3][2] += av.w * bv.z; acc[3][3] += av.w * bv.w;
        }
        __syncthreads();
    }

#pragma unroll
    for (int i = 0; i < 4; i++) {
        int d = d0 + (ty << 2) + i;
#pragma unroll
        for (int j = 0; j < 4; j++) {
            int e = e0 + (tx << 2) + j;
            g_kv[((size_t)b * DD + d) * DD + e] = acc[i][j];
        }
    }
}

// ---------------------------------------------------------------------------
// K6: out[b,n,e] = sigmoid(rs)/(rs+eps) * sum_d phi_q[b,n,d] * KV[b,d,e]
// 64x64 tile (n x e), BK=16 over d, per-batch.
// ---------------------------------------------------------------------------
__global__ void __launch_bounds__(256) k_out(float* __restrict__ out)
{
    __shared__ float As[16][68];   // [d][n]
    __shared__ float Bs[16][68];   // [d][e]

    const int tid = threadIdx.x;
    const int tx = tid & 15, ty = tid >> 4;
    const int n0 = blockIdx.x * 64;
    const int e0 = blockIdx.y * 64;
    const int b  = blockIdx.z;

    const int arow = tid >> 2;
    const int ac4  = (tid & 3) << 2;
    const int brow = tid >> 4;
    const int bc4  = (tid & 15) << 2;

    float acc[4][4];
#pragma unroll
    for (int i = 0; i < 4; i++)
#pragma unroll
        for (int j = 0; j < 4; j++) acc[i][j] = 0.f;

    const size_t abase  = ((size_t)b * NN + n0) * DD;
    const size_t kvbase = (size_t)b * DD * DD;

    for (int k0 = 0; k0 < DD; k0 += 16) {
        float4 a = *(const float4*)(g_phi_q + abase + (size_t)arow * DD + k0 + ac4);
        As[ac4 + 0][arow] = a.x;
        As[ac4 + 1][arow] = a.y;
        As[ac4 + 2][arow] = a.z;
        As[ac4 + 3][arow] = a.w;
        *(float4*)&Bs[brow][bc4] =
            *(const float4*)(g_kv + kvbase + (size_t)(k0 + brow) * DD + e0 + bc4);
        __syncthreads();

#pragma unroll
        for (int k = 0; k < 16; k++) {
            float4 av = *(const float4*)&As[k][ty << 2];
            float4 bv = *(const float4*)&Bs[k][tx << 2];
            acc[0][0] += av.x * bv.x; acc[0][1] += av.x * bv.y;
            acc[0][2] += av.x * bv.z; acc[0][3] += av.x * bv.w;
            acc[1][0] += av.y * bv.x; acc[1][1] += av.y * bv.y;
            acc[1][2] += av.y * bv.z; acc[1][3] += av.y * bv.w;
            acc[2][0] += av.z * bv.x; acc[2][1] += av.z * bv.y;
            acc[2][2] += av.z * bv.z; acc[2][3] += av.z * bv.w;
            acc[3][0] += av.w * bv.x; acc[3][1] += av.w * bv.y;
            acc[3][2] += av.w * bv.z; acc[3][3] += av.w * bv.w;
        }
        __syncthreads();
    }

#pragma unroll
    for (int i = 0; i < 4; i++) {
        int n = n0 + (ty << 2) + i;
        float rs = g_rs[b * NN + n];
        float sc = sigmoidf_(rs) / (rs + EPSF);
#pragma unroll
        for (int j = 0; j < 4; j++) {
            out[((size_t)b * NN + n) * DD + e0 + (tx << 2) + j] = acc[i][j] * sc;
        }
    }
}

// ---------------------------------------------------------------------------
extern "C" void kernel_launch(void* const* d_in, const int* in_sizes, int n_in,
                              void* d_out, int out_size)
{
    const float* Q  = (const float*)d_in[0];
    const float* K  = (const float*)d_in[1];
    const float* V  = (const float*)d_in[2];
    const float* Wq = (const float*)d_in[3];
    const float* bq = (const float*)d_in[4];
    const float* Wk = (const float*)d_in[5];
    const float* bk = (const float*)d_in[6];
    float* out = (float*)d_out;

    dim3 blk(256);

    // phi_q / phi_k
    k_phi<<<dim3((BB * NN) / 64, DD / 64), blk>>>(Q, Wq, bq, 0);
    k_phi<<<dim3((BB * NN) / 64, DD / 64), blk>>>(K, Wk, bk, 1);

    // column sums of phi_k
    k_colpart<<<dim3(BB, NSPL), blk>>>();
    k_csmerge<<<BB, DD>>>();

    // softmax stats over sequence dim
    k_statpart<<<dim3(BB, NSPL), blk>>>(V);
    k_statmerge<<<BB, DD>>>();

    // row sums of phi_q
    k_rowsum<<<(BB * NN) / 8, blk>>>();

    // KV = phi_k^T @ V_b   (V_b on the fly)
    k_kv<<<dim3(DD / 64, DD / 64, BB), blk>>>(V);

    // output GEMM + gate
    k_out<<<dim3(NN / 64, DD / 64, BB), blk>>>(out);
}

// round 3
// speedup vs baseline: 1.0008x; 1.0008x over previous
#include <cuda_runtime.h>

#define BB 16
#define NN 4096
#define DD 256
#define EPSF 1e-6f
#define NSPL 16
#define NPER (NN / NSPL)   // 256

// ---------------- scratch (device globals; allocation-free) ----------------
__device__ float g_phi_q[(size_t)BB * NN * DD];   // 64 MB
__device__ float g_phi_k[(size_t)BB * NN * DD];   // 64 MB
__device__ float g_pcs[BB * NSPL * DD];
__device__ float g_pm [BB * NSPL * DD];
__device__ float g_ps [BB * NSPL * DD];
__device__ float g_cs [BB * DD];
__device__ float g_mx [BB * DD];
__device__ float g_sm [BB * DD];
__device__ float g_rs [BB * NN];
__device__ float g_kv [(size_t)BB * DD * DD];     // 4 MB

__device__ __forceinline__ float sigmoidf_(float x) { return 1.f / (1.f + __expf(-x)); }

// ---------------- packed f32x2 helpers (2 FMAs per FMA-pipe slot) ----------
typedef unsigned long long u64t;

__device__ __forceinline__ void fma2(u64t& d, u64t a, u64t b) {
    asm("fma.rn.f32x2 %0, %1, %2, %0;" : "+l"(d) : "l"(a), "l"(b));
}
__device__ __forceinline__ u64t pack2(float lo, float hi) {
    u64t r; asm("mov.b64 %0, {%1, %2};" : "=l"(r) : "f"(lo), "f"(hi)); return r;
}
__device__ __forceinline__ float2 unpack2(u64t v) {
    float2 r; asm("mov.b64 {%0, %1}, %2;" : "=f"(r.x), "=f"(r.y) : "l"(v)); return r;
}

// ---------------------------------------------------------------------------
// K1: phi = sigmoid(X @ W + b). M = B*N = 65536, N = K = 256.
// 64x64 block tile, 4x4 per thread (rows packed in f32x2 pairs), BK=16.
// ---------------------------------------------------------------------------
__global__ void __launch_bounds__(256)
k_phi(const float* __restrict__ X, const float* __restrict__ W,
      const float* __restrict__ bias, int which)
{
    __shared__ float As[16][68];   // [k][m], padded
    __shared__ float Bs[16][68];   // [k][e], padded

    float* out = which ? g_phi_k : g_phi_q;

    const int tid = threadIdx.x;
    const int tx = tid & 15, ty = tid >> 4;
    const int m0 = blockIdx.x * 64;
    const int e0 = blockIdx.y * 64;

    const int arow = tid >> 2;
    const int ac4  = (tid & 3) << 2;
    const int brow = tid >> 4;
    const int bc4  = (tid & 15) << 2;

    u64t acc[2][4];   // [row-pair][col]; .lo = row 2*0, .hi = row 2*0+1 within pair
#pragma unroll
    for (int i = 0; i < 2; i++)
#pragma unroll
        for (int j = 0; j < 4; j++) acc[i][j] = 0ull;

    for (int k0 = 0; k0 < DD; k0 += 16) {
        float4 a = *(const float4*)(X + (size_t)(m0 + arow) * DD + k0 + ac4);
        As[ac4 + 0][arow] = a.x;
        As[ac4 + 1][arow] = a.y;
        As[ac4 + 2][arow] = a.z;
        As[ac4 + 3][arow] = a.w;
        *(float4*)&Bs[brow][bc4] =
            *(const float4*)(W + (size_t)(k0 + brow) * DD + e0 + bc4);
        __syncthreads();

#pragma unroll
        for (int k = 0; k < 16; k++) {
            float4 av = *(const float4*)&As[k][ty << 2];
            float4 bv = *(const float4*)&Bs[k][tx << 2];
            u64t a01 = pack2(av.x, av.y);
            u64t a23 = pack2(av.z, av.w);
            u64t b0 = pack2(bv.x, bv.x);
            u64t b1 = pack2(bv.y, bv.y);
            u64t b2 = pack2(bv.z, bv.z);
            u64t b3 = pack2(bv.w, bv.w);
            fma2(acc[0][0], a01, b0); fma2(acc[0][1], a01, b1);
            fma2(acc[0][2], a01, b2); fma2(acc[0][3], a01, b3);
            fma2(acc[1][0], a23, b0); fma2(acc[1][1], a23, b1);
            fma2(acc[1][2], a23, b2); fma2(acc[1][3], a23, b3);
        }
        __syncthreads();
    }

#pragma unroll
    for (int ip = 0; ip < 2; ip++) {
#pragma unroll
        for (int j = 0; j < 4; j++) {
            float2 v = unpack2(acc[ip][j]);
            int e = e0 + (tx << 2) + j;
            float bb = bias[e];
            int m = m0 + (ty << 2) + ip * 2;
            out[(size_t)m * DD + e]       = sigmoidf_(v.x + bb);
            out[(size_t)(m + 1) * DD + e] = sigmoidf_(v.y + bb);
        }
    }
}

// ---------------------------------------------------------------------------
// K2a: partial column sums of phi_k over n  (per (b, split, e))
// ---------------------------------------------------------------------------
__global__ void __launch_bounds__(256) k_colpart()
{
    const int b = blockIdx.x, spl = blockIdx.y, e = threadIdx.x;
    const float* p = g_phi_k + ((size_t)b * NN + spl * NPER) * DD + e;
    float s = 0.f;
#pragma unroll 8
    for (int n = 0; n < NPER; n++) s += p[(size_t)n * DD];
    g_pcs[(b * NSPL + spl) * DD + e] = s;
}

// K2b: merge partial column sums
__global__ void __launch_bounds__(256) k_csmerge()
{
    const int b = blockIdx.x, e = threadIdx.x;
    float s = 0.f;
#pragma unroll
    for (int spl = 0; spl < NSPL; spl++) s += g_pcs[(b * NSPL + spl) * DD + e];
    g_cs[b * DD + e] = s;
}

// ---------------------------------------------------------------------------
// K3a: partial online softmax stats of x = phi_k * V / (colsum + eps) over n
// ---------------------------------------------------------------------------
__global__ void __launch_bounds__(256) k_statpart(const float* __restrict__ V)
{
    const int b = blockIdx.x, spl = blockIdx.y, e = threadIdx.x;
    const float inv = 1.f / (g_cs[b * DD + e] + EPSF);
    const size_t off = ((size_t)b * NN + spl * NPER) * DD + e;
    const float* pk = g_phi_k + off;
    const float* pv = V + off;

    float mx = -1e30f, s = 0.f;
    for (int n = 0; n < NPER; n++) {
        float x = pk[(size_t)n * DD] * pv[(size_t)n * DD] * inv;
        if (x > mx) {
            s = s * __expf(mx - x) + 1.f;
            mx = x;
        } else {
            s += __expf(x - mx);
        }
    }
    const int idx = (b * NSPL + spl) * DD + e;
    g_pm[idx] = mx;
    g_ps[idx] = s;
}

// K3b: merge partial softmax stats
__global__ void __launch_bounds__(256) k_statmerge()
{
    const int b = blockIdx.x, e = threadIdx.x;
    float M = -1e30f;
#pragma unroll
    for (int spl = 0; spl < NSPL; spl++)
        M = fmaxf(M, g_pm[(b * NSPL + spl) * DD + e]);
    float S = 0.f;
#pragma unroll
    for (int spl = 0; spl < NSPL; spl++) {
        const int idx = (b * NSPL + spl) * DD + e;
        S += g_ps[idx] * __expf(g_pm[idx] - M);
    }
    g_mx[b * DD + e] = M;
    g_sm[b * DD + e] = S;
}

// ---------------------------------------------------------------------------
// K4: row sums of phi_q over d (one warp per row)
// ---------------------------------------------------------------------------
__global__ void __launch_bounds__(256) k_rowsum()
{
    const int row  = blockIdx.x * 8 + (threadIdx.x >> 5);
    const int lane = threadIdx.x & 31;
    const float* p = g_phi_q + (size_t)row * DD;
    float s = 0.f;
#pragma unroll
    for (int i = 0; i < 8; i++) s += p[lane + i * 32];
#pragma unroll
    for (int o = 16; o > 0; o >>= 1) s += __shfl_down_sync(0xffffffffu, s, o);
    if (lane == 0) g_rs[row] = s;
}

// ---------------------------------------------------------------------------
// K5: KV[b,d,e] = sum_n phi_k[b,n,d] * V_b[b,n,e], V_b built on the fly:
//     V_b = exp(phi_k*V/(cs+eps) - m) / s
// 64x64 tile (d x e), BK=32 over n, per-batch. f32x2 inner loop.
// ---------------------------------------------------------------------------
__global__ void __launch_bounds__(256) k_kv(const float* __restrict__ V)
{
    __shared__ float As[32][68];   // [n][d]
    __shared__ float Bs[32][68];   // [n][e]  (V_b tile)
    __shared__ float sInv[64], sM[64], sIS[64];

    const int tid = threadIdx.x;
    const int tx = tid & 15, ty = tid >> 4;
    const int d0 = blockIdx.x * 64;
    const int e0 = blockIdx.y * 64;
    const int b  = blockIdx.z;

    if (tid < 64) {
        int e = e0 + tid;
        sInv[tid] = 1.f / (g_cs[b * DD + e] + EPSF);
        sM[tid]   = g_mx[b * DD + e];
        sIS[tid]  = 1.f / g_sm[b * DD + e];
    }
    __syncthreads();

    u64t acc[2][4];
#pragma unroll
    for (int i = 0; i < 2; i++)
#pragma unroll
        for (int j = 0; j < 4; j++) acc[i][j] = 0ull;

    const size_t base = (size_t)b * NN * DD;

    for (int n0 = 0; n0 < NN; n0 += 32) {
#pragma unroll
        for (int it = 0; it < 2; it++) {
            int idx = tid + it * 256;
            int nl  = idx >> 4;
            int c4  = (idx & 15) << 2;
            size_t off = base + (size_t)(n0 + nl) * DD;

            *(float4*)&As[nl][c4] = *(const float4*)(g_phi_k + off + d0 + c4);

            float4 pk = *(const float4*)(g_phi_k + off + e0 + c4);
            float4 vv = *(const float4*)(V + off + e0 + c4);
            float4 o;
            o.x = __expf(pk.x * vv.x * sInv[c4 + 0] - sM[c4 + 0]) * sIS[c4 + 0];
            o.y = __expf(pk.y * vv.y * sInv[c4 + 1] - sM[c4 + 1]) * sIS[c4 + 1];
            o.z = __expf(pk.z * vv.z * sInv[c4 + 2] - sM[c4 + 2]) * sIS[c4 + 2];
            o.w = __expf(pk.w * vv.w * sInv[c4 + 3] - sM[c4 + 3]) * sIS[c4 + 3];
            *(float4*)&Bs[nl][c4] = o;
        }
        __syncthreads();

#pragma unroll
        for (int k = 0; k < 32; k++) {
            float4 av = *(const float4*)&As[k][ty << 2];
            float4 bv = *(const float4*)&Bs[k][tx << 2];
            u64t a01 = pack2(av.x, av.y);
            u64t a23 = pack2(av.z, av.w);
            u64t b0 = pack2(bv.x, bv.x);
            u64t b1 = pack2(bv.y, bv.y);
            u64t b2 = pack2(bv.z, bv.z);
            u64t b3 = pack2(bv.w, bv.w);
            fma2(acc[0][0], a01, b0); fma2(acc[0][1], a01, b1);
            fma2(acc[0][2], a01, b2); fma2(acc[0][3], a01, b3);
            fma2(acc[1][0], a23, b0); fma2(acc[1][1], a23, b1);
            fma2(acc[1][2], a23, b2); fma2(acc[1][3], a23, b3);
        }
        __syncthreads();
    }

#pragma unroll
    for (int ip = 0; ip < 2; ip++) {
#pragma unroll
        for (int j = 0; j < 4; j++) {
            float2 v = unpack2(acc[ip][j]);
            int d = d0 + (ty << 2) + ip * 2;
            int e = e0 + (tx << 2) + j;
            g_kv[((size_t)b * DD + d) * DD + e]     = v.x;
            g_kv[((size_t)b * DD + d + 1) * DD + e] = v.y;
        }
    }
}

// ---------------------------------------------------------------------------
// K6: out[b,n,e] = sigmoid(rs)/(rs+eps) * sum_d phi_q[b,n,d] * KV[b,d,e]
// 64x64 tile (n x e), BK=16 over d, per-batch. f32x2 inner loop.
// ---------------------------------------------------------------------------
__global__ void __launch_bounds__(256) k_out(float* __restrict__ out)
{
    __shared__ float As[16][68];   // [d][n]
    __shared__ float Bs[16][68];   // [d][e]

    const int tid = threadIdx.x;
    const int tx = tid & 15, ty = tid >> 4;
    const int n0 = blockIdx.x * 64;
    const int e0 = blockIdx.y * 64;
    const int b  = blockIdx.z;

    const int arow = tid >> 2;
    const int ac4  = (tid & 3) << 2;
    const int brow = tid >> 4;
    const int bc4  = (tid & 15) << 2;

    u64t acc[2][4];
#pragma unroll
    for (int i = 0; i < 2; i++)
#pragma unroll
        for (int j = 0; j < 4; j++) acc[i][j] = 0ull;

    const size_t abase  = ((size_t)b * NN + n0) * DD;
    const size_t kvbase = (size_t)b * DD * DD;

    for (int k0 = 0; k0 < DD; k0 += 16) {
        float4 a = *(const float4*)(g_phi_q + abase + (size_t)arow * DD + k0 + ac4);
        As[ac4 + 0][arow] = a.x;
        As[ac4 + 1][arow] = a.y;
        As[ac4 + 2][arow] = a.z;
        As[ac4 + 3][arow] = a.w;
        *(float4*)&Bs[brow][bc4] =
            *(const float4*)(g_kv + kvbase + (size_t)(k0 + brow) * DD + e0 + bc4);
        __syncthreads();

#pragma unroll
        for (int k = 0; k < 16; k++) {
            float4 av = *(const float4*)&As[k][ty << 2];
            float4 bv = *(const float4*)&Bs[k][tx << 2];
            u64t a01 = pack2(av.x, av.y);
            u64t a23 = pack2(av.z, av.w);
            u64t b0 = pack2(bv.x, bv.x);
            u64t b1 = pack2(bv.y, bv.y);
            u64t b2 = pack2(bv.z, bv.z);
            u64t b3 = pack2(bv.w, bv.w);
            fma2(acc[0][0], a01, b0); fma2(acc[0][1], a01, b1);
            fma2(acc[0][2], a01, b2); fma2(acc[0][3], a01, b3);
            fma2(acc[1][0], a23, b0); fma2(acc[1][1], a23, b1);
            fma2(acc[1][2], a23, b2); fma2(acc[1][3], a23, b3);
        }
        __syncthreads();
    }

#pragma unroll
    for (int ip = 0; ip < 2; ip++) {
        int n = n0 + (ty << 2) + ip * 2;
        float rs0 = g_rs[b * NN + n];
        float rs1 = g_rs[b * NN + n + 1];
        float sc0 = sigmoidf_(rs0) / (rs0 + EPSF);
        float sc1 = sigmoidf_(rs1) / (rs1 + EPSF);
#pragma unroll
        for (int j = 0; j < 4; j++) {
            float2 v = unpack2(acc[ip][j]);
            int e = e0 + (tx << 2) + j;
            out[((size_t)b * NN + n) * DD + e]     = v.x * sc0;
            out[((size_t)b * NN + n + 1) * DD + e] = v.y * sc1;
        }
    }
}

// ---------------------------------------------------------------------------
extern "C" void kernel_launch(void* const* d_in, const int* in_sizes, int n_in,
                              void* d_out, int out_size)
{
    const float* Q  = (const float*)d_in[0];
    const float* K  = (const float*)d_in[1];
    const float* V  = (const float*)d_in[2];
    const float* Wq = (const float*)d_in[3];
    const float* bq = (const float*)d_in[4];
    const float* Wk = (const float*)d_in[5];
    const float* bk = (const float*)d_in[6];
    float* out = (float*)d_out;

    dim3 blk(256);

    // phi_q / phi_k
    k_phi<<<dim3((BB * NN) / 64, DD / 64), blk>>>(Q, Wq, bq, 0);
    k_phi<<<dim3((BB * NN) / 64, DD / 64), blk>>>(K, Wk, bk, 1);

    // column sums of phi_k
    k_colpart<<<dim3(BB, NSPL), blk>>>();
    k_csmerge<<<BB, DD>>>();

    // softmax stats over sequence dim
    k_statpart<<<dim3(BB, NSPL), blk>>>(V);
    k_statmerge<<<BB, DD>>>();

    // row sums of phi_q
    k_rowsum<<<(BB * NN) / 8, blk>>>();

    // KV = phi_k^T @ V_b   (V_b on the fly)
    k_kv<<<dim3(DD / 64, DD / 64, BB), blk>>>(V);

    // output GEMM + gate
    k_out<<<dim3(NN / 64, DD / 64, BB), blk>>>(out);
}

// round 4
// speedup vs baseline: 1.1425x; 1.1416x over previous
#include <cuda_runtime.h>

#define BB 16
#define NN 4096
#define DD 256
#define EPSF 1e-6f
#define NSPL 16
#define NPER (NN / NSPL)   // 256
#define KSPL 4             // split-K factor for k_kv
#define NKV  (NN / KSPL)   // 1024

// ---------------- scratch (device globals; allocation-free) ----------------
__device__ float g_phi_q[(size_t)BB * NN * DD];   // 64 MB
__device__ float g_phi_k[(size_t)BB * NN * DD];   // 64 MB
__device__ float g_E    [(size_t)BB * NN * DD];   // 64 MB  (unnormalized softmax numerators)
__device__ float g_pcs[BB * NSPL * DD];
__device__ float g_ps [BB * NSPL * DD];
__device__ float g_cs [BB * DD];
__device__ float g_sm [BB * DD];                  // softmax denominators
__device__ float g_rs [BB * NN];
__device__ float g_kvp[(size_t)KSPL * BB * DD * DD];  // 16.8 MB partial KV
__device__ float g_kv [(size_t)BB * DD * DD];     // 4 MB

__device__ __forceinline__ float sigmoidf_(float x) { return 1.f / (1.f + __expf(-x)); }

// FMA-pipe exp (no MUFU). |x| <= ~10 here; deg-7 Taylor on reduced arg, rel err ~5e-9.
__device__ __forceinline__ float fast_exp(float x) {
    float y = x * 1.4426950408889634f;
    float n = rintf(y);
    float f = (y - n) * 0.6931471805599453f;       // |f| <= 0.3466
    float p = 1.9841270e-4f;                        // 1/5040
    p = fmaf(p, f, 1.3888889e-3f);
    p = fmaf(p, f, 8.3333333e-3f);
    p = fmaf(p, f, 4.1666667e-2f);
    p = fmaf(p, f, 1.6666667e-1f);
    p = fmaf(p, f, 0.5f);
    p = fmaf(p, f, 1.0f);
    p = fmaf(p, f, 1.0f);
    return p * __int_as_float(((int)n + 127) << 23);
}

// ---------------- packed f32x2 helpers (2 FMAs per FMA-pipe slot) ----------
typedef unsigned long long u64t;
__device__ __forceinline__ void fma2(u64t& d, u64t a, u64t b) {
    asm("fma.rn.f32x2 %0, %1, %2, %0;" : "+l"(d) : "l"(a), "l"(b));
}
__device__ __forceinline__ u64t pack2(float lo, float hi) {
    u64t r; asm("mov.b64 %0, {%1, %2};" : "=l"(r) : "f"(lo), "f"(hi)); return r;
}
__device__ __forceinline__ float2 unpack2(u64t v) {
    float2 r; asm("mov.b64 {%0, %1}, %2;" : "=f"(r.x), "=f"(r.y) : "l"(v)); return r;
}

// 8x8-per-thread inner step: a = 8 rows (broadcast), b = 8 cols (4 e-pairs)
#define MMA_STEP(As_, Bs_, k_)                                                  \
    {                                                                           \
        const float4* Ak = (const float4*)As_[k_];                              \
        const float4* Bk = (const float4*)Bs_[k_];                              \
        float4 a0 = Ak[ty * 2], a1 = Ak[ty * 2 + 1];                            \
        float4 b0 = Bk[tx * 2], b1 = Bk[tx * 2 + 1];                            \
        u64t bp0 = pack2(b0.x, b0.y), bp1 = pack2(b0.z, b0.w);                  \
        u64t bp2 = pack2(b1.x, b1.y), bp3 = pack2(b1.z, b1.w);                  \
        u64t ab;                                                                \
        ab = pack2(a0.x, a0.x);                                                 \
        fma2(acc[0][0], ab, bp0); fma2(acc[0][1], ab, bp1);                     \
        fma2(acc[0][2], ab, bp2); fma2(acc[0][3], ab, bp3);                     \
        ab = pack2(a0.y, a0.y);                                                 \
        fma2(acc[1][0], ab, bp0); fma2(acc[1][1], ab, bp1);                     \
        fma2(acc[1][2], ab, bp2); fma2(acc[1][3], ab, bp3);                     \
        ab = pack2(a0.z, a0.z);                                                 \
        fma2(acc[2][0], ab, bp0); fma2(acc[2][1], ab, bp1);                     \
        fma2(acc[2][2], ab, bp2); fma2(acc[2][3], ab, bp3);                     \
        ab = pack2(a0.w, a0.w);                                                 \
        fma2(acc[3][0], ab, bp0); fma2(acc[3][1], ab, bp1);                     \
        fma2(acc[3][2], ab, bp2); fma2(acc[3][3], ab, bp3);                     \
        ab = pack2(a1.x, a1.x);                                                 \
        fma2(acc[4][0], ab, bp0); fma2(acc[4][1], ab, bp1);                     \
        fma2(acc[4][2], ab, bp2); fma2(acc[4][3], ab, bp3);                     \
        ab = pack2(a1.y, a1.y);                                                 \
        fma2(acc[5][0], ab, bp0); fma2(acc[5][1], ab, bp1);                     \
        fma2(acc[5][2], ab, bp2); fma2(acc[5][3], ab, bp3);                     \
        ab = pack2(a1.z, a1.z);                                                 \
        fma2(acc[6][0], ab, bp0); fma2(acc[6][1], ab, bp1);                     \
        fma2(acc[6][2], ab, bp2); fma2(acc[6][3], ab, bp3);                     \
        ab = pack2(a1.w, a1.w);                                                 \
        fma2(acc[7][0], ab, bp0); fma2(acc[7][1], ab, bp1);                     \
        fma2(acc[7][2], ab, bp2); fma2(acc[7][3], ab, bp3);                     \
    }

// ---------------------------------------------------------------------------
// K1: phi = sigmoid(X @ W + b). 128x128 tile, 8x8/thread, BK=8, pipelined.
// ---------------------------------------------------------------------------
__global__ void __launch_bounds__(256, 2)
k_phi(const float* __restrict__ X, const float* __restrict__ W,
      const float* __restrict__ bias, int which)
{
    __shared__ float As[8][132];   // [k][m]
    __shared__ float Bs[8][132];   // [k][e]

    float* out = which ? g_phi_k : g_phi_q;

    const int tid = threadIdx.x;
    const int tx = tid & 15, ty = tid >> 4;
    const int m0 = blockIdx.x * 128;
    const int e0 = blockIdx.y * 128;

    const int arow = tid >> 1, ak4 = (tid & 1) << 2;   // A: 128 rows x 8 k
    const int brow = tid >> 5, bc4 = (tid & 31) << 2;  // B: 8 k x 128 e

    u64t acc[8][4];
#pragma unroll
    for (int i = 0; i < 8; i++)
#pragma unroll
        for (int j = 0; j < 4; j++) acc[i][j] = 0ull;

    float4 aR = *(const float4*)(X + (size_t)(m0 + arow) * DD + ak4);
    float4 bR = *(const float4*)(W + (size_t)brow * DD + e0 + bc4);

    for (int k0 = 0; k0 < DD; k0 += 8) {
        __syncthreads();
        As[ak4 + 0][arow] = aR.x;
        As[ak4 + 1][arow] = aR.y;
        As[ak4 + 2][arow] = aR.z;
        As[ak4 + 3][arow] = aR.w;
        *(float4*)&Bs[brow][bc4] = bR;
        __syncthreads();
        if (k0 + 8 < DD) {
            aR = *(const float4*)(X + (size_t)(m0 + arow) * DD + k0 + 8 + ak4);
            bR = *(const float4*)(W + (size_t)(k0 + 8 + brow) * DD + e0 + bc4);
        }
#pragma unroll
        for (int k = 0; k < 8; k++) MMA_STEP(As, Bs, k)
    }

    const float4 bb0 = *(const float4*)(bias + e0 + tx * 8);
    const float4 bb1 = *(const float4*)(bias + e0 + tx * 8 + 4);
#pragma unroll
    for (int r = 0; r < 8; r++) {
        int m = m0 + ty * 8 + r;
        float2 v0 = unpack2(acc[r][0]), v1 = unpack2(acc[r][1]);
        float2 v2 = unpack2(acc[r][2]), v3 = unpack2(acc[r][3]);
        float4 o0, o1;
        o0.x = sigmoidf_(v0.x + bb0.x); o0.y = sigmoidf_(v0.y + bb0.y);
        o0.z = sigmoidf_(v1.x + bb0.z); o0.w = sigmoidf_(v1.y + bb0.w);
        o1.x = sigmoidf_(v2.x + bb1.x); o1.y = sigmoidf_(v2.y + bb1.y);
        o1.z = sigmoidf_(v3.x + bb1.z); o1.w = sigmoidf_(v3.y + bb1.w);
        *(float4*)(out + (size_t)m * DD + e0 + tx * 8)     = o0;
        *(float4*)(out + (size_t)m * DD + e0 + tx * 8 + 4) = o1;
    }
}

// ---------------------------------------------------------------------------
// K2a/K2b: column sums of phi_k
// ---------------------------------------------------------------------------
__global__ void __launch_bounds__(256) k_colpart()
{
    const int b = blockIdx.x, spl = blockIdx.y, e = threadIdx.x;
    const float* p = g_phi_k + ((size_t)b * NN + spl * NPER) * DD + e;
    float s = 0.f;
#pragma unroll 8
    for (int n = 0; n < NPER; n++) s += p[(size_t)n * DD];
    g_pcs[(b * NSPL + spl) * DD + e] = s;
}

__global__ void __launch_bounds__(256) k_csmerge()
{
    const int b = blockIdx.x, e = threadIdx.x;
    float s = 0.f;
#pragma unroll
    for (int spl = 0; spl < NSPL; spl++) s += g_pcs[(b * NSPL + spl) * DD + e];
    g_cs[b * DD + e] = s;
}

// ---------------------------------------------------------------------------
// K3: E = exp(phi_k * V / (cs+eps))  (no max shift; x bounded), + partial
// column sums of E (softmax denominators). FMA-pipe exp, zero MUFU.
// ---------------------------------------------------------------------------
__global__ void __launch_bounds__(256) k_expE(const float* __restrict__ V)
{
    const int b = blockIdx.x, spl = blockIdx.y, e = threadIdx.x;
    const float inv = 1.f / (g_cs[b * DD + e] + EPSF);
    const size_t off = ((size_t)b * NN + spl * NPER) * DD + e;
    const float* pk = g_phi_k + off;
    const float* pv = V + off;
    float* pe = g_E + off;

    float s = 0.f;
#pragma unroll 4
    for (int n = 0; n < NPER; n++) {
        float E = fast_exp(pk[(size_t)n * DD] * pv[(size_t)n * DD] * inv);
        pe[(size_t)n * DD] = E;
        s += E;
    }
    g_ps[(b * NSPL + spl) * DD + e] = s;
}

__global__ void __launch_bounds__(256) k_esum()
{
    const int b = blockIdx.x, e = threadIdx.x;
    float s = 0.f;
#pragma unroll
    for (int spl = 0; spl < NSPL; spl++) s += g_ps[(b * NSPL + spl) * DD + e];
    g_sm[b * DD + e] = s;
}

// ---------------------------------------------------------------------------
// K4: row sums of phi_q over d (one warp per row)
// ---------------------------------------------------------------------------
__global__ void __launch_bounds__(256) k_rowsum()
{
    const int row  = blockIdx.x * 8 + (threadIdx.x >> 5);
    const int lane = threadIdx.x & 31;
    const float* p = g_phi_q + (size_t)row * DD;
    float s = 0.f;
#pragma unroll
    for (int i = 0; i < 8; i++) s += p[lane + i * 32];
#pragma unroll
    for (int o = 16; o > 0; o >>= 1) s += __shfl_down_sync(0xffffffffu, s, o);
    if (lane == 0) g_rs[row] = s;
}

// ---------------------------------------------------------------------------
// K5: partial KV[spl][b,d,e] = sum_{n in slice} phi_k[b,n,d] * E[b,n,e]
// 128x128 tile, 8x8/thread, BK=8, split-K=4. Pure FMA (no expf).
// ---------------------------------------------------------------------------
__global__ void __launch_bounds__(256, 2) k_kv()
{
    __shared__ float As[8][132];   // [n][d]
    __shared__ float Bs[8][132];   // [n][e]

    const int tid = threadIdx.x;
    const int tx = tid & 15, ty = tid >> 4;
    const int d0 = blockIdx.x * 128;
    const int e0 = blockIdx.y * 128;
    const int b  = blockIdx.z >> 2;
    const int spl = blockIdx.z & 3;
    const int nbase = spl * NKV;

    const int nl = tid >> 5, c4 = (tid & 31) << 2;  // 8 n x 128 cols

    u64t acc[8][4];
#pragma unroll
    for (int i = 0; i < 8; i++)
#pragma unroll
        for (int j = 0; j < 4; j++) acc[i][j] = 0ull;

    const size_t base = (size_t)b * NN * DD;

    float4 aR = *(const float4*)(g_phi_k + base + (size_t)(nbase + nl) * DD + d0 + c4);
    float4 bR = *(const float4*)(g_E     + base + (size_t)(nbase + nl) * DD + e0 + c4);

    for (int n0 = nbase; n0 < nbase + NKV; n0 += 8) {
        __syncthreads();
        *(float4*)&As[nl][c4] = aR;
        *(float4*)&Bs[nl][c4] = bR;
        __syncthreads();
        if (n0 + 8 < nbase + NKV) {
            aR = *(const float4*)(g_phi_k + base + (size_t)(n0 + 8 + nl) * DD + d0 + c4);
            bR = *(const float4*)(g_E     + base + (size_t)(n0 + 8 + nl) * DD + e0 + c4);
        }
#pragma unroll
        for (int k = 0; k < 8; k++) MMA_STEP(As, Bs, k)
    }

    float* dst = g_kvp + (((size_t)spl * BB + b) * DD) * DD;
#pragma unroll
    for (int r = 0; r < 8; r++) {
        int d = d0 + ty * 8 + r;
        float2 v0 = unpack2(acc[r][0]), v1 = unpack2(acc[r][1]);
        float2 v2 = unpack2(acc[r][2]), v3 = unpack2(acc[r][3]);
        float4 o0 = {v0.x, v0.y, v1.x, v1.y};
        float4 o1 = {v2.x, v2.y, v3.x, v3.y};
        *(float4*)(dst + (size_t)d * DD + e0 + tx * 8)     = o0;
        *(float4*)(dst + (size_t)d * DD + e0 + tx * 8 + 4) = o1;
    }
}

// K5b: merge split-K partials and apply softmax denominator: KV /= sm[e]
__global__ void __launch_bounds__(256) k_kvmerge()
{
    const size_t idx = (size_t)blockIdx.x * 256 + threadIdx.x;  // over BB*DD*DD
    const size_t stride = (size_t)BB * DD * DD;
    const int e = (int)(idx & (DD - 1));
    const int b = (int)(idx >> 16);  // DD*DD = 65536
    float s = g_kvp[idx] + g_kvp[stride + idx] + g_kvp[2 * stride + idx]
            + g_kvp[3 * stride + idx];
    g_kv[idx] = s / g_sm[b * DD + e];
}

// ---------------------------------------------------------------------------
// K6: out[b,n,e] = sigmoid(rs)/(rs+eps) * sum_d phi_q[b,n,d] * KV[b,d,e]
// 128x128 tile, 8x8/thread, BK=8.
// ---------------------------------------------------------------------------
__global__ void __launch_bounds__(256, 2) k_out(float* __restrict__ out)
{
    __shared__ float As[8][132];   // [d][n]
    __shared__ float Bs[8][132];   // [d][e]

    const int tid = threadIdx.x;
    const int tx = tid & 15, ty = tid >> 4;
    const int n0 = blockIdx.x * 128;
    const int e0 = blockIdx.y * 128;
    const int b  = blockIdx.z;

    const int arow = tid >> 1, ak4 = (tid & 1) << 2;
    const int brow = tid >> 5, bc4 = (tid & 31) << 2;

    u64t acc[8][4];
#pragma unroll
    for (int i = 0; i < 8; i++)
#pragma unroll
        for (int j = 0; j < 4; j++) acc[i][j] = 0ull;

    const size_t abase  = ((size_t)b * NN + n0) * DD;
    const size_t kvbase = (size_t)b * DD * DD;

    float4 aR = *(const float4*)(g_phi_q + abase + (size_t)arow * DD + ak4);
    float4 bR = *(const float4*)(g_kv + kvbase + (size_t)brow * DD + e0 + bc4);

    for (int k0 = 0; k0 < DD; k0 += 8) {
        __syncthreads();
        As[ak4 + 0][arow] = aR.x;
        As[ak4 + 1][arow] = aR.y;
        As[ak4 + 2][arow] = aR.z;
        As[ak4 + 3][arow] = aR.w;
        *(float4*)&Bs[brow][bc4] = bR;
        __syncthreads();
        if (k0 + 8 < DD) {
            aR = *(const float4*)(g_phi_q + abase + (size_t)arow * DD + k0 + 8 + ak4);
            bR = *(const float4*)(g_kv + kvbase + (size_t)(k0 + 8 + brow) * DD + e0 + bc4);
        }
#pragma unroll
        for (int k = 0; k < 8; k++) MMA_STEP(As, Bs, k)
    }

#pragma unroll
    for (int r = 0; r < 8; r++) {
        int n = n0 + ty * 8 + r;
        float rs = g_rs[b * NN + n];
        float sc = sigmoidf_(rs) / (rs + EPSF);
        float2 v0 = unpack2(acc[r][0]), v1 = unpack2(acc[r][1]);
        float2 v2 = unpack2(acc[r][2]), v3 = unpack2(acc[r][3]);
        float4 o0 = {v0.x * sc, v0.y * sc, v1.x * sc, v1.y * sc};
        float4 o1 = {v2.x * sc, v2.y * sc, v3.x * sc, v3.y * sc};
        *(float4*)(out + ((size_t)b * NN + n) * DD + e0 + tx * 8)     = o0;
        *(float4*)(out + ((size_t)b * NN + n) * DD + e0 + tx * 8 + 4) = o1;
    }
}

// ---------------------------------------------------------------------------
extern "C" void kernel_launch(void* const* d_in, const int* in_sizes, int n_in,
                              void* d_out, int out_size)
{
    const float* Q  = (const float*)d_in[0];
    const float* K  = (const float*)d_in[1];
    const float* V  = (const float*)d_in[2];
    const float* Wq = (const float*)d_in[3];
    const float* bq = (const float*)d_in[4];
    const float* Wk = (const float*)d_in[5];
    const float* bk = (const float*)d_in[6];
    float* out = (float*)d_out;

    dim3 blk(256);

    k_phi<<<dim3((BB * NN) / 128, DD / 128), blk>>>(Q, Wq, bq, 0);
    k_phi<<<dim3((BB * NN) / 128, DD / 128), blk>>>(K, Wk, bk, 1);

    k_colpart<<<dim3(BB, NSPL), blk>>>();
    k_csmerge<<<BB, DD>>>();

    k_expE<<<dim3(BB, NSPL), blk>>>(V);
    k_esum<<<BB, DD>>>();

    k_rowsum<<<(BB * NN) / 8, blk>>>();

    k_kv<<<dim3(DD / 128, DD / 128, BB * KSPL), blk>>>();
    k_kvmerge<<<(BB * DD * DD) / 256, blk>>>();

    k_out<<<dim3(NN / 128, DD / 128, BB), blk>>>(out);
}

// round 7
// speedup vs baseline: 1.9922x; 1.7437x over previous
#include <cuda_runtime.h>
#include <cuda_bf16.h>

#define BB 16
#define NN 4096
#define DD 256
#define BN (BB * NN)
#define EPSF 1e-6f
#define KSPL 4
#define NKV (NN / KSPL)

typedef unsigned short u16;
typedef unsigned int u32;

// ---------------- scratch (device globals; allocation-free) ----------------
__device__ u16 g_wqt_h[DD * DD], g_wqt_l[DD * DD];       // WqT [e,k]
__device__ u16 g_wkt_h[DD * DD], g_wkt_l[DD * DD];       // WkT [e,k]
__device__ u16 g_phiq_h[(size_t)BN * DD], g_phiq_l[(size_t)BN * DD];   // [n,e]
__device__ u16 g_phikt_h[(size_t)BN * DD], g_phikt_l[(size_t)BN * DD]; // [b,e,n]
__device__ u16 g_e_h[(size_t)BN * DD], g_e_l[(size_t)BN * DD];         // E^T [b,e,n]
__device__ float g_vt[(size_t)BN * DD];                   // V^T [b,e,n]
__device__ float g_sm[BB * DD];                           // softmax denominators
__device__ float g_rs[BB * NN];                           // phi_q row sums
__device__ float g_kvp[(size_t)KSPL * BB * DD * DD];      // partial KV^T [spl,b,e,d]
__device__ u16 g_kvt_h[(size_t)BB * DD * DD], g_kvt_l[(size_t)BB * DD * DD]; // KV^T [b,e,d]

// ---------------- helpers ----------------
__device__ __forceinline__ float sigmoidf_(float x) { return 1.f / (1.f + __expf(-x)); }

__device__ __forceinline__ u32 smem_u32(const void* p) {
    u32 a;
    asm("{ .reg .u64 t; cvta.to.shared.u64 t, %1; cvt.u32.u64 %0, t; }" : "=r"(a) : "l"(p));
    return a;
}

// store fp32 pair as planar bf16 hi/lo (packed u32 stores)
__device__ __forceinline__ void store_hl(u16* ph, u16* pl, size_t idx, float v0, float v1) {
    __nv_bfloat162 h = __floats2bfloat162_rn(v0, v1);
    float2 hf = __bfloat1622float2(h);
    __nv_bfloat162 l = __floats2bfloat162_rn(v0 - hf.x, v1 - hf.y);
    *(u32*)(ph + idx) = *(u32*)&h;
    *(u32*)(pl + idx) = *(u32*)&l;
}

#define MMA16816(cc, aa, b0, b1)                                               \
    asm volatile("mma.sync.aligned.m16n8k16.row.col.f32.bf16.bf16.f32 "        \
                 "{%0,%1,%2,%3}, {%4,%5,%6,%7}, {%8,%9}, {%0,%1,%2,%3};"       \
                 : "+f"((cc)[0]), "+f"((cc)[1]), "+f"((cc)[2]), "+f"((cc)[3])  \
                 : "r"((aa)[0]), "r"((aa)[1]), "r"((aa)[2]), "r"((aa)[3]),     \
                   "r"(b0), "r"(b1))

#define LDSM4(rr, addr)                                                        \
    asm volatile("ldmatrix.sync.aligned.m8n8.x4.shared.b16 {%0,%1,%2,%3}, [%4];" \
                 : "=r"((rr)[0]), "=r"((rr)[1]), "=r"((rr)[2]), "=r"((rr)[3])  \
                 : "r"(addr))

// ---- staging: 128 rows x 32 k into padded smem (row stride 40 u16 = 80B) ----
__device__ __forceinline__ void stage_b16(const u16* __restrict__ gh,
                                          const u16* __restrict__ gl,
                                          size_t ldg, u16* sh, u16* sl, int tid) {
    int row = tid >> 1, half = tid & 1;
    const uint4* ph = (const uint4*)(gh + (size_t)row * ldg + half * 16);
    const uint4* pl = (const uint4*)(gl + (size_t)row * ldg + half * 16);
    uint4 h0 = ph[0], h1 = ph[1];
    uint4 l0 = pl[0], l1 = pl[1];
    uint4* dh = (uint4*)(sh + row * 40 + half * 16);
    uint4* dl = (uint4*)(sl + row * 40 + half * 16);
    dh[0] = h0; dh[1] = h1;
    dl[0] = l0; dl[1] = l1;
}

__device__ __forceinline__ void cvt2(float x, float y, u32& ho, u32& lo) {
    __nv_bfloat162 h = __floats2bfloat162_rn(x, y);
    float2 hf = __bfloat1622float2(h);
    __nv_bfloat162 l = __floats2bfloat162_rn(x - hf.x, y - hf.y);
    ho = *(u32*)&h; lo = *(u32*)&l;
}

__device__ __forceinline__ void stage_f32(const float* __restrict__ g,
                                          size_t ldg, u16* sh, u16* sl, int tid) {
    int row = tid >> 1, half = tid & 1;
    const float4* p = (const float4*)(g + (size_t)row * ldg + half * 16);
    float4 v0 = p[0], v1 = p[1], v2 = p[2], v3 = p[3];
    uint4 H0, H1, L0, L1;
    cvt2(v0.x, v0.y, H0.x, L0.x); cvt2(v0.z, v0.w, H0.y, L0.y);
    cvt2(v1.x, v1.y, H0.z, L0.z); cvt2(v1.z, v1.w, H0.w, L0.w);
    cvt2(v2.x, v2.y, H1.x, L1.x); cvt2(v2.z, v2.w, H1.y, L1.y);
    cvt2(v3.x, v3.y, H1.z, L1.z); cvt2(v3.z, v3.w, H1.w, L1.w);
    uint4* dh = (uint4*)(sh + row * 40 + half * 16);
    uint4* dl = (uint4*)(sl + row * 40 + half * 16);
    dh[0] = H0; dh[1] = H1;
    dl[0] = L0; dl[1] = L1;
}

#define SMEM_DECL                                                              \
    __shared__ __align__(16) u16 sAh[128 * 40], sAl[128 * 40],                 \
                                 sBh[128 * 40], sBl[128 * 40];

#define MMAALL(AF, BF)                                                         \
    _Pragma("unroll") for (int mi = 0; mi < 4; mi++)                           \
    _Pragma("unroll") for (int nj = 0; nj < 4; nj++)                           \
        MMA16816(c[mi][nj], AF[mi], BF[nj >> 1][nj & 1], BF[nj >> 1][(nj & 1) + 2]);

// 128x128 block tile, 8 warps (2m x 4n), warp tile 64x32, K staged by 32.
// Variadic: the stage body may contain top-level commas.
#define GEMM_CORE(KTOT, ...)                                                   \
    float c[4][4][4];                                                          \
    _Pragma("unroll") for (int i_ = 0; i_ < 4; i_++)                           \
    _Pragma("unroll") for (int j_ = 0; j_ < 4; j_++)                           \
    _Pragma("unroll") for (int r_ = 0; r_ < 4; r_++) c[i_][j_][r_] = 0.f;      \
    const int lane = tid & 31, widx = tid >> 5;                                \
    const int wm = widx >> 2, wn = widx & 3;                                   \
    const u32 frow = ((u32)(lane & 15)) * 80 + ((u32)(lane >> 4)) * 16;        \
    const u32 uAh = smem_u32(sAh) + wm * 64 * 80 + frow;                       \
    const u32 uAl = smem_u32(sAl) + wm * 64 * 80 + frow;                       \
    const u32 uBh = smem_u32(sBh) + wn * 32 * 80 + frow;                       \
    const u32 uBl = smem_u32(sBl) + wn * 32 * 80 + frow;                       \
    for (int kt = 0; kt < (KTOT); kt += 32) {                                  \
        __syncthreads();                                                       \
        { __VA_ARGS__ }                                                        \
        __syncthreads();                                                       \
        _Pragma("unroll")                                                      \
        for (int s = 0; s < 2; s++) {                                          \
            u32 ah[4][4], al[4][4], bb[2][4];                                  \
            LDSM4(bb[0], uBh + s * 32);                                        \
            LDSM4(bb[1], uBh + 16 * 80 + s * 32);                              \
            _Pragma("unroll") for (int mi = 0; mi < 4; mi++) {                 \
                LDSM4(ah[mi], uAh + mi * 16 * 80 + s * 32);                    \
                LDSM4(al[mi], uAl + mi * 16 * 80 + s * 32);                    \
            }                                                                  \
            MMAALL(ah, bb)                                                     \
            MMAALL(al, bb)                                                     \
            LDSM4(bb[0], uBl + s * 32);                                        \
            LDSM4(bb[1], uBl + 16 * 80 + s * 32);                              \
            MMAALL(ah, bb)                                                     \
        }                                                                      \
    }

// Variadic: epilogue bodies may contain top-level commas.
#define EPILOOP(...)                                                           \
    _Pragma("unroll") for (int mi = 0; mi < 4; mi++)                           \
    _Pragma("unroll") for (int nj = 0; nj < 4; nj++) {                         \
        int r0 = wm * 64 + mi * 16 + (lane >> 2);                              \
        int cc0 = wn * 32 + nj * 8 + ((lane & 3) << 1);                        \
        __VA_ARGS__                                                            \
    }

// ---------------------------------------------------------------------------
// prep: WT hi/lo [e,k] from W [k,e]
// ---------------------------------------------------------------------------
__global__ void k_wprep(const float* __restrict__ Wq, const float* __restrict__ Wk)
{
    int e = blockIdx.x, k = threadIdx.x;
    float q = Wq[(size_t)k * DD + e];
    float kk = Wk[(size_t)k * DD + e];
    __nv_bfloat16 qh = __float2bfloat16(q);
    __nv_bfloat16 ql = __float2bfloat16(q - __bfloat162float(qh));
    __nv_bfloat16 kh = __float2bfloat16(kk);
    __nv_bfloat16 kl = __float2bfloat16(kk - __bfloat162float(kh));
    g_wqt_h[e * DD + k] = *(u16*)&qh;  g_wqt_l[e * DD + k] = *(u16*)&ql;
    g_wkt_h[e * DD + k] = *(u16*)&kh;  g_wkt_l[e * DD + k] = *(u16*)&kl;
}

// V transpose: V[b,n,e] -> V^T[b,e,n]
__global__ void k_transV(const float* __restrict__ V)
{
    __shared__ float t[32][33];
    int n0 = blockIdx.x * 32, e0 = blockIdx.y * 32, b = blockIdx.z;
    int tx = threadIdx.x, ty = threadIdx.y;
#pragma unroll
    for (int i = 0; i < 4; i++)
        t[ty + 8 * i][tx] = V[((size_t)b * NN + n0 + ty + 8 * i) * DD + e0 + tx];
    __syncthreads();
#pragma unroll
    for (int i = 0; i < 4; i++)
        g_vt[((size_t)b * DD + e0 + ty + 8 * i) * NN + n0 + tx] = t[tx][ty + 8 * i];
}

// ---------------------------------------------------------------------------
// phi_q[n,e] = sigmoid(Q@Wq + bq).  A=Q[n,k] (m=n), B=WqT[e,k] (n-dim=e)
// ---------------------------------------------------------------------------
__global__ void __launch_bounds__(256, 2)
k_phiq(const float* __restrict__ Q, const float* __restrict__ bq)
{
    SMEM_DECL
    const int tid = threadIdx.x;
    const int m0 = blockIdx.x * 128;   // global n
    const int e0 = blockIdx.y * 128;

    GEMM_CORE(DD,
        stage_f32(Q + (size_t)m0 * DD + kt, DD, sAh, sAl, tid);
        stage_b16(g_wqt_h + (size_t)e0 * DD + kt, g_wqt_l + (size_t)e0 * DD + kt,
                  DD, sBh, sBl, tid);
    )

    EPILOOP(
        int e = e0 + cc0;
        float2 bqe = *(const float2*)(bq + e);
        int n0g = m0 + r0;
        store_hl(g_phiq_h, g_phiq_l, (size_t)n0g * DD + e,
                 sigmoidf_(c[mi][nj][0] + bqe.x), sigmoidf_(c[mi][nj][1] + bqe.y));
        store_hl(g_phiq_h, g_phiq_l, (size_t)(n0g + 8) * DD + e,
                 sigmoidf_(c[mi][nj][2] + bqe.x), sigmoidf_(c[mi][nj][3] + bqe.y));
    )
}

// ---------------------------------------------------------------------------
// phi_k^T[b,e,n] = sigmoid(K@Wk + bk)^T.  A=WkT[e,k] (m=e), B=K[n,k] (n-dim=n)
// ---------------------------------------------------------------------------
__global__ void __launch_bounds__(256, 2)
k_phik(const float* __restrict__ Kin, const float* __restrict__ bk)
{
    SMEM_DECL
    const int tid = threadIdx.x;
    const int n0 = blockIdx.x * 128;   // global n
    const int m0e = blockIdx.y * 128;  // e

    GEMM_CORE(DD,
        stage_b16(g_wkt_h + (size_t)m0e * DD + kt, g_wkt_l + (size_t)m0e * DD + kt,
                  DD, sAh, sAl, tid);
        stage_f32(Kin + (size_t)n0 * DD + kt, DD, sBh, sBl, tid);
    )

    EPILOOP(
        int er = m0e + r0;
        int gn = n0 + cc0;
        int b = gn >> 12;
        int nl = gn & (NN - 1);
        float b0 = bk[er];
        float b1 = bk[er + 8];
        store_hl(g_phikt_h, g_phikt_l, ((size_t)b * DD + er) * NN + nl,
                 sigmoidf_(c[mi][nj][0] + b0), sigmoidf_(c[mi][nj][1] + b0));
        store_hl(g_phikt_h, g_phikt_l, ((size_t)b * DD + er + 8) * NN + nl,
                 sigmoidf_(c[mi][nj][2] + b1), sigmoidf_(c[mi][nj][3] + b1));
    )
}

// ---------------------------------------------------------------------------
// per (b,e): colsum(phi_k) -> inv; E = exp(phi_k*V*inv); rowsum(E) -> sm
// ---------------------------------------------------------------------------
__global__ void __launch_bounds__(256) k_cs_exp()
{
    __shared__ float red[256];
    const int e = blockIdx.x, b = blockIdx.y, tid = threadIdx.x;
    const size_t base = ((size_t)b * DD + e) * NN;
    const u16* ph = g_phikt_h + base;
    const u16* pl = g_phikt_l + base;
    const float* vt = g_vt + base;

    float pkx[8], pky[8];
    float s = 0.f;
#pragma unroll
    for (int i = 0; i < 8; i++) {
        int n = i * 512 + tid * 2;
        u32 hp = *(const u32*)(ph + n);
        u32 lp = *(const u32*)(pl + n);
        float2 hf = __bfloat1622float2(*(__nv_bfloat162*)&hp);
        float2 lf = __bfloat1622float2(*(__nv_bfloat162*)&lp);
        pkx[i] = hf.x + lf.x;
        pky[i] = hf.y + lf.y;
        s += pkx[i] + pky[i];
    }
    red[tid] = s; __syncthreads();
    for (int o = 128; o > 0; o >>= 1) { if (tid < o) red[tid] += red[tid + o]; __syncthreads(); }
    const float inv = 1.f / (red[0] + EPSF);
    __syncthreads();

    float s2 = 0.f;
#pragma unroll
    for (int i = 0; i < 8; i++) {
        int n = i * 512 + tid * 2;
        float2 vv = *(const float2*)(vt + n);
        float E0 = __expf(pkx[i] * vv.x * inv);
        float E1 = __expf(pky[i] * vv.y * inv);
        store_hl(g_e_h, g_e_l, base + n, E0, E1);
        s2 += E0 + E1;
    }
    red[tid] = s2; __syncthreads();
    for (int o = 128; o > 0; o >>= 1) { if (tid < o) red[tid] += red[tid + o]; __syncthreads(); }
    if (tid == 0) g_sm[b * DD + e] = red[0];
}

// row sums of phi_q over d (warp per row)
__global__ void __launch_bounds__(256) k_rowsum()
{
    const int row = blockIdx.x * 8 + (threadIdx.x >> 5);
    const int lane = threadIdx.x & 31;
    const u16* ph = g_phiq_h + (size_t)row * DD;
    const u16* pl = g_phiq_l + (size_t)row * DD;
    float s = 0.f;
#pragma unroll
    for (int i = 0; i < 4; i++) {
        int j2 = (lane + 32 * i) * 2;
        u32 hp = *(const u32*)(ph + j2);
        u32 lp = *(const u32*)(pl + j2);
        float2 hf = __bfloat1622float2(*(__nv_bfloat162*)&hp);
        float2 lf = __bfloat1622float2(*(__nv_bfloat162*)&lp);
        s += hf.x + hf.y + lf.x + lf.y;
    }
#pragma unroll
    for (int o = 16; o > 0; o >>= 1) s += __shfl_down_sync(0xffffffffu, s, o);
    if (lane == 0) g_rs[row] = s;
}

// ---------------------------------------------------------------------------
// KV partial: kvp[spl,b,e,d] = sum_{n in slice} E^T[e,n]*phi_k^T[d,n]
// A=E^T (m=e), B=phi_k^T (n-dim=d), K=NKV.
// ---------------------------------------------------------------------------
__global__ void __launch_bounds__(256, 2) k_kv()
{
    SMEM_DECL
    const int tid = threadIdx.x;
    const int d0 = blockIdx.x * 128;
    const int e0 = blockIdx.y * 128;
    const int b = blockIdx.z >> 2;
    const int spl = blockIdx.z & 3;
    const size_t abase = ((size_t)b * DD + e0) * NN + spl * NKV;
    const size_t bbase = ((size_t)b * DD + d0) * NN + spl * NKV;

    GEMM_CORE(NKV,
        stage_b16(g_e_h + abase + kt, g_e_l + abase + kt, NN, sAh, sAl, tid);
        stage_b16(g_phikt_h + bbase + kt, g_phikt_l + bbase + kt, NN, sBh, sBl, tid);
    )

    float* dst = g_kvp + (size_t)(spl * BB + b) * DD * DD;
    EPILOOP(
        int e = e0 + r0;
        int d = d0 + cc0;
        *(float2*)(dst + (size_t)e * DD + d) = make_float2(c[mi][nj][0], c[mi][nj][1]);
        *(float2*)(dst + (size_t)(e + 8) * DD + d) = make_float2(c[mi][nj][2], c[mi][nj][3]);
    )
}

// merge split-K, divide by sm[b,e], split-store KV^T [b,e,d]
__global__ void __launch_bounds__(256) k_kvmerge()
{
    const size_t idx = (size_t)blockIdx.x * 256 + threadIdx.x;
    const size_t S = (size_t)BB * DD * DD;
    const int e = (int)((idx >> 8) & 255);
    const int b = (int)(idx >> 16);
    float s = g_kvp[idx] + g_kvp[S + idx] + g_kvp[2 * S + idx] + g_kvp[3 * S + idx];
    float v = s / g_sm[b * DD + e];
    __nv_bfloat16 h = __float2bfloat16(v);
    __nv_bfloat16 l = __float2bfloat16(v - __bfloat162float(h));
    g_kvt_h[idx] = *(u16*)&h;
    g_kvt_l[idx] = *(u16*)&l;
}

// ---------------------------------------------------------------------------
// out[n,e] = sigmoid(rs)/(rs+eps) * sum_d phi_q[n,d]*KV^T[e,d]
// A=phi_q[n,d] (m=n), B=KV^T[e,d] (n-dim=e), K=DD.
// ---------------------------------------------------------------------------
__global__ void __launch_bounds__(256, 2) k_out(float* __restrict__ out)
{
    SMEM_DECL
    const int tid = threadIdx.x;
    const int m0 = blockIdx.x * 128;   // global n
    const int e0 = blockIdx.y * 128;
    const int b = m0 >> 12;
    const size_t abase = (size_t)m0 * DD;
    const size_t bbase = ((size_t)b * DD + e0) * DD;

    GEMM_CORE(DD,
        stage_b16(g_phiq_h + abase + kt, g_phiq_l + abase + kt, DD, sAh, sAl, tid);
        stage_b16(g_kvt_h + bbase + kt, g_kvt_l + bbase + kt, DD, sBh, sBl, tid);
    )

    EPILOOP(
        int ng = m0 + r0;
        int e = e0 + cc0;
        float rs0 = g_rs[ng];
        float rs1 = g_rs[ng + 8];
        float s0 = sigmoidf_(rs0) / (rs0 + EPSF);
        float s1 = sigmoidf_(rs1) / (rs1 + EPSF);
        *(float2*)(out + (size_t)ng * DD + e) =
            make_float2(c[mi][nj][0] * s0, c[mi][nj][1] * s0);
        *(float2*)(out + (size_t)(ng + 8) * DD + e) =
            make_float2(c[mi][nj][2] * s1, c[mi][nj][3] * s1);
    )
}

// ---------------------------------------------------------------------------
extern "C" void kernel_launch(void* const* d_in, const int* in_sizes, int n_in,
                              void* d_out, int out_size)
{
    const float* Q  = (const float*)d_in[0];
    const float* K  = (const float*)d_in[1];
    const float* V  = (const float*)d_in[2];
    const float* Wq = (const float*)d_in[3];
    const float* bq = (const float*)d_in[4];
    const float* Wk = (const float*)d_in[5];
    const float* bk = (const float*)d_in[6];
    float* out = (float*)d_out;

    k_wprep<<<DD, 256>>>(Wq, Wk);
    k_transV<<<dim3(NN / 32, DD / 32, BB), dim3(32, 8)>>>(V);

    k_phik<<<dim3(BN / 128, 2), 256>>>(K, bk);
    k_phiq<<<dim3(BN / 128, 2), 256>>>(Q, bq);

    k_cs_exp<<<dim3(DD, BB), 256>>>();
    k_rowsum<<<BN / 8, 256>>>();

    k_kv<<<dim3(2, 2, BB * KSPL), 256>>>();
    k_kvmerge<<<(BB * DD * DD) / 256, 256>>>();

    k_out<<<dim3(BN / 128, 2), 256>>>(out);
}